// round 10
// baseline (speedup 1.0000x reference)
#include <cuda_runtime.h>
#include <cuda_fp16.h>
#include <cstdint>

#define Nn 8
#define Cc 16
#define Ll 1024
#define Dd 7
#define Hh 16
#define SZ 112
#define PAD 8

// Scratch: Q/K in [bh, l, 8] fp32 tf32-rounded (Q pre-scaled by log2(e)/32);
// V in [bh, l, 8] fp32 with pad dim = 1.0 (becomes softmax denom via MMA).
__device__ float g_Q[Nn * Hh * Ll * PAD];
__device__ float g_K[Nn * Hh * Ll * PAD];
__device__ float g_V[Nn * Hh * Ll * PAD];

__device__ __forceinline__ float tf32r(float x) {
    uint32_t u; asm("cvt.rna.tf32.f32 %0, %1;" : "=r"(u) : "f"(x));
    return __uint_as_float(u);
}
// Pack two fp32 into one f16x2 register (lo = a, hi = b).
__device__ __forceinline__ uint32_t f16x2(float a, float b) {
    uint32_t r;
    asm("cvt.rn.f16x2.f32 %0, %1, %2;" : "=r"(r) : "f"(b), "f"(a));
    return r;
}
// Packed fp16 2^x (one MUFU op for two values).
__device__ __forceinline__ uint32_t ex2h2(uint32_t x) {
    uint32_t y; asm("ex2.approx.f16x2 %0, %1;" : "=r"(y) : "r"(x)); return y;
}
// D += A(16x8) @ B(8x8), tf32 in, fp32 accum.
__device__ __forceinline__ void mma_tf32_k8(float& d0, float& d1, float& d2, float& d3,
                                            uint32_t a0, uint32_t a1, uint32_t a2, uint32_t a3,
                                            uint32_t b0, uint32_t b1) {
    asm volatile(
        "mma.sync.aligned.m16n8k8.row.col.f32.tf32.tf32.f32 "
        "{%0,%1,%2,%3}, {%4,%5,%6,%7}, {%8,%9}, {%0,%1,%2,%3};"
        : "+f"(d0), "+f"(d1), "+f"(d2), "+f"(d3)
        : "r"(a0), "r"(a1), "r"(a2), "r"(a3), "r"(b0), "r"(b1));
}
// D += A(16x16) @ B(16x8), fp16 in, fp32 accum.
__device__ __forceinline__ void mma_f16_k16(float& d0, float& d1, float& d2, float& d3,
                                            uint32_t a0, uint32_t a1, uint32_t a2, uint32_t a3,
                                            uint32_t b0, uint32_t b1) {
    asm volatile(
        "mma.sync.aligned.m16n8k16.row.col.f32.f16.f16.f32 "
        "{%0,%1,%2,%3}, {%4,%5,%6,%7}, {%8,%9}, {%0,%1,%2,%3};"
        : "+f"(d0), "+f"(d1), "+f"(d2), "+f"(d3)
        : "r"(a0), "r"(a1), "r"(a2), "r"(a3), "r"(b0), "r"(b1));
}

// ---------------------------------------------------------------------------
// Projection: q/k/v = xf @ W^T + b -> [bh, l, 8].
// ---------------------------------------------------------------------------
__global__ __launch_bounds__(256) void proj_kernel(
    const float* __restrict__ x,
    const float* __restrict__ Wq, const float* __restrict__ bq,
    const float* __restrict__ Wk, const float* __restrict__ bk,
    const float* __restrict__ Wv, const float* __restrict__ bv)
{
    extern __shared__ float sm[];
    float* Wt = sm;
    float* As = sm + 112 * 113;
    float* bs = As + 64 * 113;

    const int z = blockIdx.y;
    const float* W = (z == 0) ? Wq : ((z == 1) ? Wk : Wv);
    const float* b = (z == 0) ? bq : ((z == 1) ? bk : bv);
    float* dst     = (z == 0) ? g_Q : ((z == 1) ? g_K : g_V);
    const float scale = (z == 0) ? (1.4426950408889634f / 32.0f) : 1.0f;
    const float padv  = (z == 2) ? 1.0f : 0.0f;
    const bool  do_tf = (z != 2);

    const int tid  = threadIdx.x;
    const int row0 = blockIdx.x * 64;

    for (int e = tid; e < SZ * SZ; e += 256) {
        int o = e / SZ, i = e - o * SZ;
        Wt[i * 113 + o] = W[e];
    }
    for (int e = tid; e < 64 * SZ; e += 256) {
        int r = e / SZ, i = e - r * SZ;
        int row = row0 + r;
        int n = row >> 10, l = row & 1023;
        int c = i / Dd, dd = i - c * Dd;
        As[r * 113 + i] = x[(((n * Cc + c) << 10) + l) * Dd + dd];
    }
    if (tid < SZ) bs[tid] = b[tid];
    __syncthreads();

    const int rr = tid >> 4, oc = tid & 15;
    float acc[4][7];
#pragma unroll
    for (int k = 0; k < 4; ++k)
#pragma unroll
        for (int j = 0; j < 7; ++j) acc[k][j] = 0.0f;

#pragma unroll 4
    for (int i = 0; i < SZ; ++i) {
        float w[7];
#pragma unroll
        for (int j = 0; j < 7; ++j) w[j] = Wt[i * 113 + oc * 7 + j];
#pragma unroll
        for (int k = 0; k < 4; ++k) {
            float a = As[(rr * 4 + k) * 113 + i];
#pragma unroll
            for (int j = 0; j < 7; ++j) acc[k][j] = fmaf(a, w[j], acc[k][j]);
        }
    }
#pragma unroll
    for (int k = 0; k < 4; ++k) {
        int row = row0 + rr * 4 + k;
        int n = row >> 10, l = row & 1023;
        float4* p = (float4*)(dst + (((n * Hh + oc) << 10) + l) * PAD);
        float r0 = (acc[k][0] + bs[oc * 7 + 0]) * scale;
        float r1 = (acc[k][1] + bs[oc * 7 + 1]) * scale;
        float r2 = (acc[k][2] + bs[oc * 7 + 2]) * scale;
        float r3 = (acc[k][3] + bs[oc * 7 + 3]) * scale;
        float r4 = (acc[k][4] + bs[oc * 7 + 4]) * scale;
        float r5 = (acc[k][5] + bs[oc * 7 + 5]) * scale;
        float r6 = (acc[k][6] + bs[oc * 7 + 6]) * scale;
        if (do_tf) {
            r0 = tf32r(r0); r1 = tf32r(r1); r2 = tf32r(r2); r3 = tf32r(r3);
            r4 = tf32r(r4); r5 = tf32r(r5); r6 = tf32r(r6);
        }
        p[0] = make_float4(r0, r1, r2, r3);
        p[1] = make_float4(r4, r5, r6, padv);
    }
}

// ---------------------------------------------------------------------------
// Warp-MMA attention. Per 16-key step: 2 tf32 QK MMAs -> 4 f16x2 packs ->
// 4 packed ex2.f16x2 (MUFU halved) -> 1 k16 fp16 AV MMA. All in-loop SMEM
// loads are paired LDS.64 with conflict-free strides:
//   KTp[dim][516] float2 = (K[k0+g][dim], K[k0+8+g][dim])      (33024 B)
//   Vq[(4c+t)*12+g] uint2 = (vb0, vb1) pre-packed fp16 V pairs (24576 B)
// V pad dim = 1 -> output col 7 = softmax denominator.
// ---------------------------------------------------------------------------
__global__ __launch_bounds__(256) void attn_kernel(float* __restrict__ out)
{
    extern __shared__ char smem[];
    float2* KTp = (float2*)smem;              // [8][516]
    uint2*  Vq  = (uint2*)(smem + 33024);     // [256][12] (8 used per row)

    const int tid = threadIdx.x;
    const int wid = tid >> 5, lid = tid & 31;
    const int g = lid >> 2, t = lid & 3;
    const int qt = blockIdx.x;
    const int bh = blockIdx.y;

    // Stage K pairs: KTp[d][c*8+g] = (K[16c+g][d], K[16c+8+g][d]).
    const float* gK = g_K + bh * Ll * PAD;
    for (int e = tid; e < 4096; e += 256) {
        int d = e >> 9, j = e & 511;
        int c = j >> 3, gg = j & 7;
        KTp[d * 516 + j] = make_float2(gK[(c * 16 + gg) * 8 + d],
                                       gK[(c * 16 + 8 + gg) * 8 + d]);
    }
    // Stage V pairs: thread gi handles 4 key rows -> 8 uint2 entries.
    {
        const float4* gV4 = (const float4*)(g_V + bh * Ll * PAD);
        int gi = tid;                       // 0..255
        int c = gi >> 2, tt = gi & 3;
        int kA = c * 16 + 2 * tt, kB = kA + 8;
        float4 a0 = gV4[kA * 2], a1 = gV4[kA * 2 + 1];
        float4 b0 = gV4[kA * 2 + 2], b1 = gV4[kA * 2 + 3];
        float4 c0 = gV4[kB * 2], c1 = gV4[kB * 2 + 1];
        float4 d0 = gV4[kB * 2 + 2], d1 = gV4[kB * 2 + 3];
        uint2* dstp = Vq + gi * 12;
        dstp[0] = make_uint2(f16x2(a0.x, b0.x), f16x2(c0.x, d0.x));
        dstp[1] = make_uint2(f16x2(a0.y, b0.y), f16x2(c0.y, d0.y));
        dstp[2] = make_uint2(f16x2(a0.z, b0.z), f16x2(c0.z, d0.z));
        dstp[3] = make_uint2(f16x2(a0.w, b0.w), f16x2(c0.w, d0.w));
        dstp[4] = make_uint2(f16x2(a1.x, b1.x), f16x2(c1.x, d1.x));
        dstp[5] = make_uint2(f16x2(a1.y, b1.y), f16x2(c1.y, d1.y));
        dstp[6] = make_uint2(f16x2(a1.z, b1.z), f16x2(c1.z, d1.z));
        dstp[7] = make_uint2(f16x2(a1.w, b1.w), f16x2(c1.w, d1.w));
    }

    // Q A-fragment (rows wid*16 + {g, g+8}, k-dims {t, t+4}).
    const float* qb = g_Q + (bh * Ll + qt * 128 + wid * 16) * PAD;
    const uint32_t qa0 = __float_as_uint(qb[g * 8 + t]);
    const uint32_t qa1 = __float_as_uint(qb[(g + 8) * 8 + t]);
    const uint32_t qa2 = __float_as_uint(qb[g * 8 + t + 4]);
    const uint32_t qa3 = __float_as_uint(qb[(g + 8) * 8 + t + 4]);
    __syncthreads();

    float o0 = 0.f, o1 = 0.f, o2 = 0.f, o3 = 0.f;   // out frag (cols=dims, col7=denom)

    const float2* K0 = KTp + t * 516 + g;
    const float2* K4 = KTp + (t + 4) * 516 + g;
    const uint2*  Vt = Vq + t * 12 + g;

#pragma unroll 4
    for (int c = 0; c < 64; ++c) {
        // --- QK: two 8-key tf32 MMAs (paired K loads) ---
        float2 fa = K0[c * 8];
        float2 fb = K4[c * 8];
        float sa0 = 0.f, sa1 = 0.f, sa2 = 0.f, sa3 = 0.f;
        float sb0 = 0.f, sb1 = 0.f, sb2 = 0.f, sb3 = 0.f;
        mma_tf32_k8(sa0, sa1, sa2, sa3, qa0, qa1, qa2, qa3,
                    __float_as_uint(fa.x), __float_as_uint(fb.x));
        mma_tf32_k8(sb0, sb1, sb2, sb3, qa0, qa1, qa2, qa3,
                    __float_as_uint(fa.y), __float_as_uint(fb.y));

        // --- pack scores to f16x2, packed MUFU exp (A-frag layout direct) ---
        uint32_t wa0 = ex2h2(f16x2(sa0, sa1));
        uint32_t wa1 = ex2h2(f16x2(sa2, sa3));
        uint32_t wa2 = ex2h2(f16x2(sb0, sb1));
        uint32_t wa3 = ex2h2(f16x2(sb2, sb3));

        // --- AV: one k16 fp16 MMA; paired V B-frag load ---
        uint2 v = Vt[c * 48];            // (c*4)*12
        mma_f16_k16(o0, o1, o2, o3, wa0, wa1, wa2, wa3, v.x, v.y);
    }

    // Denominator = col 7, held by lane (g,3) in o1 (row g) / o3 (row g+8).
    float sum0 = __shfl_sync(0xffffffffu, o1, (lid & ~3) | 3);
    float sum1 = __shfl_sync(0xffffffffu, o3, (lid & ~3) | 3);
    float i0 = 1.0f / sum0, i1 = 1.0f / sum1;

    const int row = bh * Ll + qt * 128 + wid * 16 + g;
    float* p0 = out + row * Dd;
    float* p1 = out + (row + 8) * Dd;
    p0[2 * t] = o0 * i0;
    p1[2 * t] = o2 * i1;
    if (t < 3) {
        p0[2 * t + 1] = o1 * i0;
        p1[2 * t + 1] = o3 * i1;
    }
}

extern "C" void kernel_launch(void* const* d_in, const int* in_sizes, int n_in,
                              void* d_out, int out_size)
{
    const float* x  = (const float*)d_in[0];
    const float* Wq = (const float*)d_in[1];
    const float* bq = (const float*)d_in[2];
    const float* Wk = (const float*)d_in[3];
    const float* bk = (const float*)d_in[4];
    const float* Wv = (const float*)d_in[5];
    const float* bv = (const float*)d_in[6];

    cudaFuncSetAttribute(proj_kernel, cudaFuncAttributeMaxDynamicSharedMemorySize, 98304);
    cudaFuncSetAttribute(attn_kernel, cudaFuncAttributeMaxDynamicSharedMemorySize, 57600);

    proj_kernel<<<dim3(128, 3, 1), 256, 98304>>>(x, Wq, bq, Wk, bk, Wv, bv);
    attn_kernel<<<dim3(8, 128, 1), 256, 57600>>>((float*)d_out);
}

// round 11
// speedup vs baseline: 1.0789x; 1.0789x over previous
#include <cuda_runtime.h>
#include <cuda_fp16.h>
#include <cstdint>

#define Nn 8
#define Cc 16
#define Ll 1024
#define Dd 7
#define Hh 16
#define SZ 112
#define PAD 8

// Scratch: Q/K in [bh, l, 8] fp32 tf32-rounded (Q pre-scaled by log2(e)/32);
// V in [bh, l, 8] fp32 with pad dim = 1.0 (becomes softmax denom via MMA).
__device__ float g_Q[Nn * Hh * Ll * PAD];
__device__ float g_K[Nn * Hh * Ll * PAD];
__device__ float g_V[Nn * Hh * Ll * PAD];

__device__ __forceinline__ float tf32r(float x) {
    uint32_t u; asm("cvt.rna.tf32.f32 %0, %1;" : "=r"(u) : "f"(x));
    return __uint_as_float(u);
}
// Pack two fp32 into one f16x2 register (lo = a, hi = b).
__device__ __forceinline__ uint32_t f16x2(float a, float b) {
    uint32_t r;
    asm("cvt.rn.f16x2.f32 %0, %1, %2;" : "=r"(r) : "f"(b), "f"(a));
    return r;
}
// Packed fp16 2^x (one MUFU op for two values).
__device__ __forceinline__ uint32_t ex2h2(uint32_t x) {
    uint32_t y; asm("ex2.approx.f16x2 %0, %1;" : "=r"(y) : "r"(x)); return y;
}
// D += A(16x8) @ B(8x8), tf32 in, fp32 accum.
__device__ __forceinline__ void mma_tf32_k8(float& d0, float& d1, float& d2, float& d3,
                                            uint32_t a0, uint32_t a1, uint32_t a2, uint32_t a3,
                                            uint32_t b0, uint32_t b1) {
    asm volatile(
        "mma.sync.aligned.m16n8k8.row.col.f32.tf32.tf32.f32 "
        "{%0,%1,%2,%3}, {%4,%5,%6,%7}, {%8,%9}, {%0,%1,%2,%3};"
        : "+f"(d0), "+f"(d1), "+f"(d2), "+f"(d3)
        : "r"(a0), "r"(a1), "r"(a2), "r"(a3), "r"(b0), "r"(b1));
}
// D += A(16x16) @ B(16x8), fp16 in, fp32 accum.
__device__ __forceinline__ void mma_f16_k16(float& d0, float& d1, float& d2, float& d3,
                                            uint32_t a0, uint32_t a1, uint32_t a2, uint32_t a3,
                                            uint32_t b0, uint32_t b1) {
    asm volatile(
        "mma.sync.aligned.m16n8k16.row.col.f32.f16.f16.f32 "
        "{%0,%1,%2,%3}, {%4,%5,%6,%7}, {%8,%9}, {%0,%1,%2,%3};"
        : "+f"(d0), "+f"(d1), "+f"(d2), "+f"(d3)
        : "r"(a0), "r"(a1), "r"(a2), "r"(a3), "r"(b0), "r"(b1));
}

// ---------------------------------------------------------------------------
// Projection: q/k/v = xf @ W^T + b -> [bh, l, 8].
// ---------------------------------------------------------------------------
__global__ __launch_bounds__(256) void proj_kernel(
    const float* __restrict__ x,
    const float* __restrict__ Wq, const float* __restrict__ bq,
    const float* __restrict__ Wk, const float* __restrict__ bk,
    const float* __restrict__ Wv, const float* __restrict__ bv)
{
    extern __shared__ float sm[];
    float* Wt = sm;
    float* As = sm + 112 * 113;
    float* bs = As + 64 * 113;

    const int z = blockIdx.y;
    const float* W = (z == 0) ? Wq : ((z == 1) ? Wk : Wv);
    const float* b = (z == 0) ? bq : ((z == 1) ? bk : bv);
    float* dst     = (z == 0) ? g_Q : ((z == 1) ? g_K : g_V);
    const float scale = (z == 0) ? (1.4426950408889634f / 32.0f) : 1.0f;
    const float padv  = (z == 2) ? 1.0f : 0.0f;
    const bool  do_tf = (z != 2);

    const int tid  = threadIdx.x;
    const int row0 = blockIdx.x * 64;

    for (int e = tid; e < SZ * SZ; e += 256) {
        int o = e / SZ, i = e - o * SZ;
        Wt[i * 113 + o] = W[e];
    }
    for (int e = tid; e < 64 * SZ; e += 256) {
        int r = e / SZ, i = e - r * SZ;
        int row = row0 + r;
        int n = row >> 10, l = row & 1023;
        int c = i / Dd, dd = i - c * Dd;
        As[r * 113 + i] = x[(((n * Cc + c) << 10) + l) * Dd + dd];
    }
    if (tid < SZ) bs[tid] = b[tid];
    __syncthreads();

    const int rr = tid >> 4, oc = tid & 15;
    float acc[4][7];
#pragma unroll
    for (int k = 0; k < 4; ++k)
#pragma unroll
        for (int j = 0; j < 7; ++j) acc[k][j] = 0.0f;

#pragma unroll 4
    for (int i = 0; i < SZ; ++i) {
        float w[7];
#pragma unroll
        for (int j = 0; j < 7; ++j) w[j] = Wt[i * 113 + oc * 7 + j];
#pragma unroll
        for (int k = 0; k < 4; ++k) {
            float a = As[(rr * 4 + k) * 113 + i];
#pragma unroll
            for (int j = 0; j < 7; ++j) acc[k][j] = fmaf(a, w[j], acc[k][j]);
        }
    }
#pragma unroll
    for (int k = 0; k < 4; ++k) {
        int row = row0 + rr * 4 + k;
        int n = row >> 10, l = row & 1023;
        float4* p = (float4*)(dst + (((n * Hh + oc) << 10) + l) * PAD);
        float r0 = (acc[k][0] + bs[oc * 7 + 0]) * scale;
        float r1 = (acc[k][1] + bs[oc * 7 + 1]) * scale;
        float r2 = (acc[k][2] + bs[oc * 7 + 2]) * scale;
        float r3 = (acc[k][3] + bs[oc * 7 + 3]) * scale;
        float r4 = (acc[k][4] + bs[oc * 7 + 4]) * scale;
        float r5 = (acc[k][5] + bs[oc * 7 + 5]) * scale;
        float r6 = (acc[k][6] + bs[oc * 7 + 6]) * scale;
        if (do_tf) {
            r0 = tf32r(r0); r1 = tf32r(r1); r2 = tf32r(r2); r3 = tf32r(r3);
            r4 = tf32r(r4); r5 = tf32r(r5); r6 = tf32r(r6);
        }
        p[0] = make_float4(r0, r1, r2, r3);
        p[1] = make_float4(r4, r5, r6, padv);
    }
}

// ---------------------------------------------------------------------------
// Warp-MMA attention (R9 layout, packed-fp16 exp). CTA = (qtile, bh):
// 128 q x 1024 k, 8 warps x 16 query rows. Per 16-key step:
// 2 tf32 QK MMAs -> 4 f16x2 packs -> 4 packed ex2.f16x2 (MUFU halved vs R9)
// -> 1 m16n8k16 fp16 AV MMA. V pre-packed half2 key-pairs, dim7 = 1 -> denom.
// SMEM: KT fp32 [8][1032] (33024 B) + Vp half2 [512][8] (16384 B) = 49408 B.
// ---------------------------------------------------------------------------
__global__ __launch_bounds__(256) void attn_kernel(float* __restrict__ out)
{
    extern __shared__ char smem[];
    float*   KT = (float*)smem;               // [8][1032]
    __half2* Vp = (__half2*)(smem + 33024);   // [512][8]: (V[2k],V[2k+1])[dim]

    const int tid = threadIdx.x;
    const int wid = tid >> 5, lid = tid & 31;
    const int g = lid >> 2, t = lid & 3;
    const int qt = blockIdx.x;
    const int bh = blockIdx.y;

    // Stage K^T (fp32 tf32-rounded).
    const float* gK = g_K + bh * Ll * PAD;
    for (int e = tid; e < 8192; e += 256) {
        int key = e >> 3, dim = e & 7;
        KT[dim * 1032 + key] = gK[e];
    }
    // Stage V packed: Vp[k2][dim] = half2(V[2k2][dim], V[2k2+1][dim]).
    {
        const float4* gV4 = (const float4*)(g_V + bh * Ll * PAD);
        for (int k2 = tid; k2 < 512; k2 += 256) {
            float4 e0a = gV4[k2 * 4 + 0], e0b = gV4[k2 * 4 + 1];
            float4 e1a = gV4[k2 * 4 + 2], e1b = gV4[k2 * 4 + 3];
            uint32_t* d = (uint32_t*)(Vp + k2 * 8);
            d[0] = f16x2(e0a.x, e1a.x);
            d[1] = f16x2(e0a.y, e1a.y);
            d[2] = f16x2(e0a.z, e1a.z);
            d[3] = f16x2(e0a.w, e1a.w);
            d[4] = f16x2(e0b.x, e1b.x);
            d[5] = f16x2(e0b.y, e1b.y);
            d[6] = f16x2(e0b.z, e1b.z);
            d[7] = f16x2(e0b.w, e1b.w);
        }
    }

    // Q A-fragment (rows wid*16 + {g, g+8}, k-dims {t, t+4}).
    const float* qb = g_Q + (bh * Ll + qt * 128 + wid * 16) * PAD;
    const uint32_t qa0 = __float_as_uint(qb[g * 8 + t]);
    const uint32_t qa1 = __float_as_uint(qb[(g + 8) * 8 + t]);
    const uint32_t qa2 = __float_as_uint(qb[g * 8 + t + 4]);
    const uint32_t qa3 = __float_as_uint(qb[(g + 8) * 8 + t + 4]);
    __syncthreads();

    float o0 = 0.f, o1 = 0.f, o2 = 0.f, o3 = 0.f;   // out frag (cols=dims, col7=denom)

    const uint32_t* Vpu = (const uint32_t*)Vp;
    const float* KTt0 = KT + t * 1032;
    const float* KTt4 = KT + (t + 4) * 1032;

#pragma unroll 4
    for (int c = 0; c < 64; ++c) {
        const int k0 = c * 16;
        // --- QK: two 8-key tf32 MMAs (scores in log2 domain) ---
        uint32_t ka0 = __float_as_uint(KTt0[k0 + g]);
        uint32_t ka1 = __float_as_uint(KTt4[k0 + g]);
        uint32_t kb0 = __float_as_uint(KTt0[k0 + 8 + g]);
        uint32_t kb1 = __float_as_uint(KTt4[k0 + 8 + g]);
        float sa0 = 0.f, sa1 = 0.f, sa2 = 0.f, sa3 = 0.f;
        float sb0 = 0.f, sb1 = 0.f, sb2 = 0.f, sb3 = 0.f;
        mma_tf32_k8(sa0, sa1, sa2, sa3, qa0, qa1, qa2, qa3, ka0, ka1);
        mma_tf32_k8(sb0, sb1, sb2, sb3, qa0, qa1, qa2, qa3, kb0, kb1);

        // --- pack scores to f16x2 first, then ONE packed MUFU exp per pair ---
        uint32_t wa0 = ex2h2(f16x2(sa0, sa1));
        uint32_t wa1 = ex2h2(f16x2(sa2, sa3));
        uint32_t wa2 = ex2h2(f16x2(sb0, sb1));
        uint32_t wa3 = ex2h2(f16x2(sb2, sb3));

        // --- AV: one k16 fp16 MMA; B-frag from packed V (conflict-free) ---
        uint32_t vb0 = Vpu[(c * 8 + t) * 8 + g];
        uint32_t vb1 = Vpu[(c * 8 + t + 4) * 8 + g];
        mma_f16_k16(o0, o1, o2, o3, wa0, wa1, wa2, wa3, vb0, vb1);
    }

    // Denominator = col 7, held by lane (g,3) in o1 (row g) / o3 (row g+8).
    float sum0 = __shfl_sync(0xffffffffu, o1, (lid & ~3) | 3);
    float sum1 = __shfl_sync(0xffffffffu, o3, (lid & ~3) | 3);
    float i0 = 1.0f / sum0, i1 = 1.0f / sum1;

    const int row = bh * Ll + qt * 128 + wid * 16 + g;
    float* p0 = out + row * Dd;
    float* p1 = out + (row + 8) * Dd;
    p0[2 * t] = o0 * i0;
    p1[2 * t] = o2 * i1;
    if (t < 3) {
        p0[2 * t + 1] = o1 * i0;
        p1[2 * t + 1] = o3 * i1;
    }
}

extern "C" void kernel_launch(void* const* d_in, const int* in_sizes, int n_in,
                              void* d_out, int out_size)
{
    const float* x  = (const float*)d_in[0];
    const float* Wq = (const float*)d_in[1];
    const float* bq = (const float*)d_in[2];
    const float* Wk = (const float*)d_in[3];
    const float* bk = (const float*)d_in[4];
    const float* Wv = (const float*)d_in[5];
    const float* bv = (const float*)d_in[6];

    cudaFuncSetAttribute(proj_kernel, cudaFuncAttributeMaxDynamicSharedMemorySize, 98304);
    cudaFuncSetAttribute(attn_kernel, cudaFuncAttributeMaxDynamicSharedMemorySize, 49408);

    proj_kernel<<<dim3(128, 3, 1), 256, 98304>>>(x, Wq, bq, Wk, bk, Wv, bv);
    attn_kernel<<<dim3(8, 128, 1), 256, 49408>>>((float*)d_out);
}

// round 12
// speedup vs baseline: 1.2284x; 1.1386x over previous
#include <cuda_runtime.h>
#include <cuda_fp16.h>
#include <cstdint>

#define Nn 8
#define Cc 16
#define Ll 1024
#define Dd 7
#define Hh 16
#define SZ 112
#define PAD 8

// Scratch: Q/K in [bh, l, 8] (tf32-domain; Q pre-scaled by log2(e)/32);
// V in [bh, l, 8] fp32 with pad dim = 1.0 (becomes softmax denom via MMA).
__device__ float g_Q[Nn * Hh * Ll * PAD];
__device__ float g_K[Nn * Hh * Ll * PAD];
__device__ float g_V[Nn * Hh * Ll * PAD];

__device__ __forceinline__ float tf32r(float x) {
    uint32_t u; asm("cvt.rna.tf32.f32 %0, %1;" : "=r"(u) : "f"(x));
    return __uint_as_float(u);
}
// Pack two fp32 into one f16x2 register (lo = a, hi = b).
__device__ __forceinline__ uint32_t f16x2(float a, float b) {
    uint32_t r;
    asm("cvt.rn.f16x2.f32 %0, %1, %2;" : "=r"(r) : "f"(b), "f"(a));
    return r;
}
// Packed fp16 2^x (one MUFU op for two values).
__device__ __forceinline__ uint32_t ex2h2(uint32_t x) {
    uint32_t y; asm("ex2.approx.f16x2 %0, %1;" : "=r"(y) : "r"(x)); return y;
}
// D += A(16x8) @ B(8x8), tf32 in, fp32 accum.
__device__ __forceinline__ void mma_tf32_k8(float& d0, float& d1, float& d2, float& d3,
                                            uint32_t a0, uint32_t a1, uint32_t a2, uint32_t a3,
                                            uint32_t b0, uint32_t b1) {
    asm volatile(
        "mma.sync.aligned.m16n8k8.row.col.f32.tf32.tf32.f32 "
        "{%0,%1,%2,%3}, {%4,%5,%6,%7}, {%8,%9}, {%0,%1,%2,%3};"
        : "+f"(d0), "+f"(d1), "+f"(d2), "+f"(d3)
        : "r"(a0), "r"(a1), "r"(a2), "r"(a3), "r"(b0), "r"(b1));
}
// D += A(16x16) @ B(16x8), fp16 in, fp32 accum.
__device__ __forceinline__ void mma_f16_k16(float& d0, float& d1, float& d2, float& d3,
                                            uint32_t a0, uint32_t a1, uint32_t a2, uint32_t a3,
                                            uint32_t b0, uint32_t b1) {
    asm volatile(
        "mma.sync.aligned.m16n8k16.row.col.f32.f16.f16.f32 "
        "{%0,%1,%2,%3}, {%4,%5,%6,%7}, {%8,%9}, {%0,%1,%2,%3};"
        : "+f"(d0), "+f"(d1), "+f"(d2), "+f"(d3)
        : "r"(a0), "r"(a1), "r"(a2), "r"(a3), "r"(b0), "r"(b1));
}

// ---------------------------------------------------------------------------
// Tensor-core projection: q/k/v = xf @ W^T + b -> [bh, l, 8].
// Grid (128 row-tiles of 64, 3 matrices), 256 threads (8 warps).
// Warp w: rows (w&3)*16, cols (w>>2)*56 (7 n-tiles of 8). m16n8k8 tf32.
// SMEM: Wt[112][120] transposed (B-frag bank 24t+g, conflict-free),
//       As[64][116]  (A-frag bank 20g+t, conflict-free), bias[112].
// ---------------------------------------------------------------------------
__global__ __launch_bounds__(256) void proj_kernel(
    const float* __restrict__ x,
    const float* __restrict__ Wq, const float* __restrict__ bq,
    const float* __restrict__ Wk, const float* __restrict__ bk,
    const float* __restrict__ Wv, const float* __restrict__ bv)
{
    extern __shared__ float sm[];
    float* Wt = sm;                     // [112][120]
    float* As = sm + 112 * 120;         // [64][116]
    float* bs = As + 64 * 116;          // [112]

    const int z = blockIdx.y;
    const float* W = (z == 0) ? Wq : ((z == 1) ? Wk : Wv);
    const float* b = (z == 0) ? bq : ((z == 1) ? bk : bv);
    float* dst     = (z == 0) ? g_Q : ((z == 1) ? g_K : g_V);
    const float scale = (z == 0) ? (1.4426950408889634f / 32.0f) : 1.0f;
    const float padv  = (z == 2) ? 1.0f : 0.0f;
    const bool  do_tf = (z != 2);

    const int tid  = threadIdx.x;
    const int row0 = blockIdx.x * 64;
    const int nb   = row0 >> 10;          // batch index (constant per CTA)

    // Stage W transposed, tf32-rounded: Wt[i][o] = tf32(W[o][i]).
    for (int e = tid; e < SZ * SZ; e += 256) {
        int o = e / SZ, i = e - o * SZ;
        Wt[i * 120 + o] = tf32r(W[e]);
    }
    // Stage xf tile, tf32-rounded: As[r][i] = tf32(x[n, i/7, l, i%7]).
    for (int e = tid; e < 64 * SZ; e += 256) {
        int r = e / SZ, i = e - r * SZ;
        int l = (row0 + r) & 1023;
        int c = i / Dd, dd = i - c * Dd;
        As[r * 116 + i] = tf32r(x[(((nb * Cc + c) << 10) + l) * Dd + dd]);
    }
    if (tid < SZ) bs[tid] = b[tid];
    __syncthreads();

    const int wid = tid >> 5, lid = tid & 31;
    const int g = lid >> 2, t = lid & 3;
    const int rt = wid & 3;            // 16-row tile within the 64 rows
    const int ch = wid >> 1 & 2;       // dummy to keep regs low? no:
    const int cw = wid >> 2;           // column half: cols cw*56

    const float* A0 = As + (rt * 16 + g) * 116;
    const float* A1 = A0 + 8 * 116;

    // C-frags initialized with bias (d0/d2 = col 2t, d1/d3 = col 2t+1).
    float acc[7][4];
#pragma unroll
    for (int nt = 0; nt < 7; ++nt) {
        int n0 = cw * 56 + nt * 8;
        float b0 = bs[n0 + 2 * t], b1 = bs[n0 + 2 * t + 1];
        acc[nt][0] = b0; acc[nt][1] = b1;
        acc[nt][2] = b0; acc[nt][3] = b1;
    }

#pragma unroll
    for (int ks = 0; ks < 14; ++ks) {
        const int k0 = ks * 8;
        uint32_t a0 = __float_as_uint(A0[k0 + t]);
        uint32_t a1 = __float_as_uint(A1[k0 + t]);
        uint32_t a2 = __float_as_uint(A0[k0 + t + 4]);
        uint32_t a3 = __float_as_uint(A1[k0 + t + 4]);
        const float* Bk0 = Wt + (k0 + t) * 120 + cw * 56 + g;
        const float* Bk4 = Bk0 + 4 * 120;
#pragma unroll
        for (int nt = 0; nt < 7; ++nt) {
            uint32_t b0 = __float_as_uint(Bk0[nt * 8]);
            uint32_t b1 = __float_as_uint(Bk4[nt * 8]);
            mma_tf32_k8(acc[nt][0], acc[nt][1], acc[nt][2], acc[nt][3],
                        a0, a1, a2, a3, b0, b1);
        }
    }

    // Epilogue: scatter 28 values (rows rowA/rowB, cols o0/o0+1 per n-tile).
    const int rowA = row0 + rt * 16 + g;
    const int lA = rowA & 1023, lB = lA + 8;
#pragma unroll
    for (int nt = 0; nt < 7; ++nt) {
        int o0 = cw * 56 + nt * 8 + 2 * t;
#pragma unroll
        for (int j = 0; j < 2; ++j) {
            int o = o0 + j;
            int head = o / 7, dim = o - head * 7;
            float vA = acc[nt][j]     * scale;
            float vB = acc[nt][2 + j] * scale;
            if (do_tf) { vA = tf32r(vA); vB = tf32r(vB); }
            float* base = dst + (((nb * Hh + head) << 10)) * PAD + dim;
            base[lA * PAD] = vA;
            base[lB * PAD] = vB;
        }
    }
    // Pad dims: Q/K pad = 0 (scores need a clean k-dim 8), V pad = 1 (denom).
    for (int e = tid; e < 64 * 16; e += 256) {
        int r = e >> 4, hh = e & 15;
        int l = (row0 + r) & 1023;
        dst[(((nb * Hh + hh) << 10) + l) * PAD + 7] = padv;
    }
}

// ---------------------------------------------------------------------------
// Warp-MMA attention (R11, unchanged — measured 32.5us). CTA = (qtile, bh):
// 128 q x 1024 k, 8 warps x 16 query rows. Per 16-key step:
// 2 tf32 QK MMAs -> 4 f16x2 packs -> 4 packed ex2.f16x2 -> 1 k16 fp16 AV MMA.
// V pre-packed half2 key-pairs, dim7 = 1 -> denom.
// SMEM: KT fp32 [8][1032] (33024 B) + Vp half2 [512][8] (16384 B) = 49408 B.
// ---------------------------------------------------------------------------
__global__ __launch_bounds__(256) void attn_kernel(float* __restrict__ out)
{
    extern __shared__ char smem[];
    float*   KT = (float*)smem;               // [8][1032]
    __half2* Vp = (__half2*)(smem + 33024);   // [512][8]: (V[2k],V[2k+1])[dim]

    const int tid = threadIdx.x;
    const int wid = tid >> 5, lid = tid & 31;
    const int g = lid >> 2, t = lid & 3;
    const int qt = blockIdx.x;
    const int bh = blockIdx.y;

    // Stage K^T.
    const float* gK = g_K + bh * Ll * PAD;
    for (int e = tid; e < 8192; e += 256) {
        int key = e >> 3, dim = e & 7;
        KT[dim * 1032 + key] = gK[e];
    }
    // Stage V packed: Vp[k2][dim] = half2(V[2k2][dim], V[2k2+1][dim]).
    {
        const float4* gV4 = (const float4*)(g_V + bh * Ll * PAD);
        for (int k2 = tid; k2 < 512; k2 += 256) {
            float4 e0a = gV4[k2 * 4 + 0], e0b = gV4[k2 * 4 + 1];
            float4 e1a = gV4[k2 * 4 + 2], e1b = gV4[k2 * 4 + 3];
            uint32_t* d = (uint32_t*)(Vp + k2 * 8);
            d[0] = f16x2(e0a.x, e1a.x);
            d[1] = f16x2(e0a.y, e1a.y);
            d[2] = f16x2(e0a.z, e1a.z);
            d[3] = f16x2(e0a.w, e1a.w);
            d[4] = f16x2(e0b.x, e1b.x);
            d[5] = f16x2(e0b.y, e1b.y);
            d[6] = f16x2(e0b.z, e1b.z);
            d[7] = f16x2(e0b.w, e1b.w);
        }
    }

    // Q A-fragment (rows wid*16 + {g, g+8}, k-dims {t, t+4}).
    const float* qb = g_Q + (bh * Ll + qt * 128 + wid * 16) * PAD;
    const uint32_t qa0 = __float_as_uint(qb[g * 8 + t]);
    const uint32_t qa1 = __float_as_uint(qb[(g + 8) * 8 + t]);
    const uint32_t qa2 = __float_as_uint(qb[g * 8 + t + 4]);
    const uint32_t qa3 = __float_as_uint(qb[(g + 8) * 8 + t + 4]);
    __syncthreads();

    float o0 = 0.f, o1 = 0.f, o2 = 0.f, o3 = 0.f;   // out frag (cols=dims, col7=denom)

    const uint32_t* Vpu = (const uint32_t*)Vp;
    const float* KTt0 = KT + t * 1032;
    const float* KTt4 = KT + (t + 4) * 1032;

#pragma unroll 4
    for (int c = 0; c < 64; ++c) {
        const int k0 = c * 16;
        // --- QK: two 8-key tf32 MMAs (scores in log2 domain) ---
        uint32_t ka0 = __float_as_uint(KTt0[k0 + g]);
        uint32_t ka1 = __float_as_uint(KTt4[k0 + g]);
        uint32_t kb0 = __float_as_uint(KTt0[k0 + 8 + g]);
        uint32_t kb1 = __float_as_uint(KTt4[k0 + 8 + g]);
        float sa0 = 0.f, sa1 = 0.f, sa2 = 0.f, sa3 = 0.f;
        float sb0 = 0.f, sb1 = 0.f, sb2 = 0.f, sb3 = 0.f;
        mma_tf32_k8(sa0, sa1, sa2, sa3, qa0, qa1, qa2, qa3, ka0, ka1);
        mma_tf32_k8(sb0, sb1, sb2, sb3, qa0, qa1, qa2, qa3, kb0, kb1);

        // --- pack scores to f16x2, one packed MUFU exp per pair ---
        uint32_t wa0 = ex2h2(f16x2(sa0, sa1));
        uint32_t wa1 = ex2h2(f16x2(sa2, sa3));
        uint32_t wa2 = ex2h2(f16x2(sb0, sb1));
        uint32_t wa3 = ex2h2(f16x2(sb2, sb3));

        // --- AV: one k16 fp16 MMA; B-frag from packed V (conflict-free) ---
        uint32_t vb0 = Vpu[(c * 8 + t) * 8 + g];
        uint32_t vb1 = Vpu[(c * 8 + t + 4) * 8 + g];
        mma_f16_k16(o0, o1, o2, o3, wa0, wa1, wa2, wa3, vb0, vb1);
    }

    // Denominator = col 7, held by lane (g,3) in o1 (row g) / o3 (row g+8).
    float sum0 = __shfl_sync(0xffffffffu, o1, (lid & ~3) | 3);
    float sum1 = __shfl_sync(0xffffffffu, o3, (lid & ~3) | 3);
    float i0 = 1.0f / sum0, i1 = 1.0f / sum1;

    const int row = bh * Ll + qt * 128 + wid * 16 + g;
    float* p0 = out + row * Dd;
    float* p1 = out + (row + 8) * Dd;
    p0[2 * t] = o0 * i0;
    p1[2 * t] = o2 * i1;
    if (t < 3) {
        p0[2 * t + 1] = o1 * i0;
        p1[2 * t + 1] = o3 * i1;
    }
}

extern "C" void kernel_launch(void* const* d_in, const int* in_sizes, int n_in,
                              void* d_out, int out_size)
{
    const float* x  = (const float*)d_in[0];
    const float* Wq = (const float*)d_in[1];
    const float* bq = (const float*)d_in[2];
    const float* Wk = (const float*)d_in[3];
    const float* bk = (const float*)d_in[4];
    const float* Wv = (const float*)d_in[5];
    const float* bv = (const float*)d_in[6];

    // SMEM: proj 112*120*4 + 64*116*4 + 448 = 83904 B; attn 49408 B.
    cudaFuncSetAttribute(proj_kernel, cudaFuncAttributeMaxDynamicSharedMemorySize, 83904);
    cudaFuncSetAttribute(attn_kernel, cudaFuncAttributeMaxDynamicSharedMemorySize, 49408);

    proj_kernel<<<dim3(128, 3, 1), 256, 83904>>>(x, Wq, bq, Wk, bk, Wv, bv);
    attn_kernel<<<dim3(8, 128, 1), 256, 49408>>>((float*)d_out);
}

// round 13
// speedup vs baseline: 1.2299x; 1.0012x over previous
#include <cuda_runtime.h>
#include <cuda_fp16.h>
#include <cstdint>

#define Nn 8
#define Cc 16
#define Ll 1024
#define Dd 7
#define Hh 16
#define SZ 112
#define PAD 8

// Scratch: Q/K in [bh, l, 8] (tf32-domain; Q pre-scaled by log2(e)/32);
// V in [bh, l, 8] fp32 with pad dim = 1.0 (becomes softmax denom via MMA).
__device__ float g_Q[Nn * Hh * Ll * PAD];
__device__ float g_K[Nn * Hh * Ll * PAD];
__device__ float g_V[Nn * Hh * Ll * PAD];

__device__ __forceinline__ float tf32r(float x) {
    uint32_t u; asm("cvt.rna.tf32.f32 %0, %1;" : "=r"(u) : "f"(x));
    return __uint_as_float(u);
}
// Pack two fp32 into one f16x2 register (lo = a, hi = b).
__device__ __forceinline__ uint32_t f16x2(float a, float b) {
    uint32_t r;
    asm("cvt.rn.f16x2.f32 %0, %1, %2;" : "=r"(r) : "f"(b), "f"(a));
    return r;
}
// Packed fp16 2^x (one MUFU op for two values).
__device__ __forceinline__ uint32_t ex2h2(uint32_t x) {
    uint32_t y; asm("ex2.approx.f16x2 %0, %1;" : "=r"(y) : "r"(x)); return y;
}
// D += A(16x8) @ B(8x8), tf32 in, fp32 accum.
__device__ __forceinline__ void mma_tf32_k8(float& d0, float& d1, float& d2, float& d3,
                                            uint32_t a0, uint32_t a1, uint32_t a2, uint32_t a3,
                                            uint32_t b0, uint32_t b1) {
    asm volatile(
        "mma.sync.aligned.m16n8k8.row.col.f32.tf32.tf32.f32 "
        "{%0,%1,%2,%3}, {%4,%5,%6,%7}, {%8,%9}, {%0,%1,%2,%3};"
        : "+f"(d0), "+f"(d1), "+f"(d2), "+f"(d3)
        : "r"(a0), "r"(a1), "r"(a2), "r"(a3), "r"(b0), "r"(b1));
}
// D += A(16x16) @ B(16x8), fp16 in, fp32 accum.
__device__ __forceinline__ void mma_f16_k16(float& d0, float& d1, float& d2, float& d3,
                                            uint32_t a0, uint32_t a1, uint32_t a2, uint32_t a3,
                                            uint32_t b0, uint32_t b1) {
    asm volatile(
        "mma.sync.aligned.m16n8k16.row.col.f32.f16.f16.f32 "
        "{%0,%1,%2,%3}, {%4,%5,%6,%7}, {%8,%9}, {%0,%1,%2,%3};"
        : "+f"(d0), "+f"(d1), "+f"(d2), "+f"(d3)
        : "r"(a0), "r"(a1), "r"(a2), "r"(a3), "r"(b0), "r"(b1));
}

// ---------------------------------------------------------------------------
// Tensor-core projection v2: q/k/v = xf @ W^T + b -> [bh, l, 8].
// Grid (64 blocks of 128 rows, 3 matrices), 256 threads (8 warps).
// W staged ONCE per CTA (o-major Wt[o*116+i]: staging STS conflict-free,
// B-frag read bank (20g+t+k0) all-distinct), then two 64-row subtiles.
// One wave: 192 CTAs at 2 CTAs/SM.
// ---------------------------------------------------------------------------
__global__ __launch_bounds__(256) void proj_kernel(
    const float* __restrict__ x,
    const float* __restrict__ Wq, const float* __restrict__ bq,
    const float* __restrict__ Wk, const float* __restrict__ bk,
    const float* __restrict__ Wv, const float* __restrict__ bv)
{
    extern __shared__ float sm[];
    float* Wt = sm;                     // [112][116] o-major: Wt[o*116+i]
    float* As = sm + 112 * 116;         // [64][116]
    float* bs = As + 64 * 116;          // [112]

    const int z = blockIdx.y;
    const float* W = (z == 0) ? Wq : ((z == 1) ? Wk : Wv);
    const float* b = (z == 0) ? bq : ((z == 1) ? bk : bv);
    float* dst     = (z == 0) ? g_Q : ((z == 1) ? g_K : g_V);
    const float scale = (z == 0) ? (1.4426950408889634f / 32.0f) : 1.0f;
    const float padv  = (z == 2) ? 1.0f : 0.0f;
    const bool  do_tf = (z != 2);

    const int tid = threadIdx.x;
    const int nb  = (blockIdx.x * 128) >> 10;   // batch (128 | 1024 -> constant)

    // Stage W o-major, tf32-rounded: Wt[o][i] = tf32(W[o][i]).
    // Consecutive e -> consecutive i -> conflict-free STS; coalesced LDG.
    for (int e = tid; e < SZ * SZ; e += 256) {
        int o = e / SZ, i = e - o * SZ;
        Wt[o * 116 + i] = tf32r(W[e]);
    }
    if (tid < SZ) bs[tid] = b[tid];

    const int wid = tid >> 5, lid = tid & 31;
    const int g = lid >> 2, t = lid & 3;
    const int rt = wid & 3;            // 16-row tile within 64 rows
    const int cw = wid >> 2;           // column half: cols cw*56

    for (int sub = 0; sub < 2; ++sub) {
        const int row0 = blockIdx.x * 128 + sub * 64;
        __syncthreads();   // W/bias ready (sub 0); As safe to overwrite (sub 1)

        // Stage xf tile, tf32-rounded: As[r][i] = tf32(x[n, i/7, l, i%7]).
        for (int e = tid; e < 64 * SZ; e += 256) {
            int r = e / SZ, i = e - r * SZ;
            int l = (row0 + r) & 1023;
            int c = i / Dd, dd = i - c * Dd;
            As[r * 116 + i] = tf32r(x[(((nb * Cc + c) << 10) + l) * Dd + dd]);
        }
        __syncthreads();

        const float* A0 = As + (rt * 16 + g) * 116;
        const float* A1 = A0 + 8 * 116;

        // C-frags init with bias (d0/d2 = col 2t, d1/d3 = col 2t+1).
        float acc[7][4];
#pragma unroll
        for (int nt = 0; nt < 7; ++nt) {
            int n0 = cw * 56 + nt * 8;
            float b0 = bs[n0 + 2 * t], b1 = bs[n0 + 2 * t + 1];
            acc[nt][0] = b0; acc[nt][1] = b1;
            acc[nt][2] = b0; acc[nt][3] = b1;
        }

#pragma unroll
        for (int ks = 0; ks < 14; ++ks) {
            const int k0 = ks * 8;
            uint32_t a0 = __float_as_uint(A0[k0 + t]);
            uint32_t a1 = __float_as_uint(A1[k0 + t]);
            uint32_t a2 = __float_as_uint(A0[k0 + t + 4]);
            uint32_t a3 = __float_as_uint(A1[k0 + t + 4]);
            const float* B0 = Wt + (cw * 56 + g) * 116 + k0;   // o-major
#pragma unroll
            for (int nt = 0; nt < 7; ++nt) {
                uint32_t b0 = __float_as_uint(B0[nt * 8 * 116 + t]);
                uint32_t b1 = __float_as_uint(B0[nt * 8 * 116 + t + 4]);
                mma_tf32_k8(acc[nt][0], acc[nt][1], acc[nt][2], acc[nt][3],
                            a0, a1, a2, a3, b0, b1);
            }
        }

        // Epilogue scatter (measured cheap): rows rowA/rowB, 2 cols per n-tile.
        const int lA = (row0 + rt * 16 + g) & 1023, lB = lA + 8;
#pragma unroll
        for (int nt = 0; nt < 7; ++nt) {
            int o0 = cw * 56 + nt * 8 + 2 * t;
#pragma unroll
            for (int j = 0; j < 2; ++j) {
                int o = o0 + j;
                int head = o / 7, dim = o - head * 7;
                float vA = acc[nt][j]     * scale;
                float vB = acc[nt][2 + j] * scale;
                if (do_tf) { vA = tf32r(vA); vB = tf32r(vB); }
                float* base = dst + (((nb * Hh + head) << 10)) * PAD + dim;
                base[lA * PAD] = vA;
                base[lB * PAD] = vB;
            }
        }
        // Pad dims: Q/K pad = 0 (clean k-dim 8), V pad = 1 (denominator).
        for (int e = tid; e < 64 * 16; e += 256) {
            int r = e >> 4, hh = e & 15;
            int l = (row0 + r) & 1023;
            dst[(((nb * Hh + hh) << 10) + l) * PAD + 7] = padv;
        }
    }
}

// ---------------------------------------------------------------------------
// Warp-MMA attention (R11/R12, unchanged — measured 31.7us).
// ---------------------------------------------------------------------------
__global__ __launch_bounds__(256) void attn_kernel(float* __restrict__ out)
{
    extern __shared__ char smem[];
    float*   KT = (float*)smem;               // [8][1032]
    __half2* Vp = (__half2*)(smem + 33024);   // [512][8]: (V[2k],V[2k+1])[dim]

    const int tid = threadIdx.x;
    const int wid = tid >> 5, lid = tid & 31;
    const int g = lid >> 2, t = lid & 3;
    const int qt = blockIdx.x;
    const int bh = blockIdx.y;

    // Stage K^T.
    const float* gK = g_K + bh * Ll * PAD;
    for (int e = tid; e < 8192; e += 256) {
        int key = e >> 3, dim = e & 7;
        KT[dim * 1032 + key] = gK[e];
    }
    // Stage V packed: Vp[k2][dim] = half2(V[2k2][dim], V[2k2+1][dim]).
    {
        const float4* gV4 = (const float4*)(g_V + bh * Ll * PAD);
        for (int k2 = tid; k2 < 512; k2 += 256) {
            float4 e0a = gV4[k2 * 4 + 0], e0b = gV4[k2 * 4 + 1];
            float4 e1a = gV4[k2 * 4 + 2], e1b = gV4[k2 * 4 + 3];
            uint32_t* d = (uint32_t*)(Vp + k2 * 8);
            d[0] = f16x2(e0a.x, e1a.x);
            d[1] = f16x2(e0a.y, e1a.y);
            d[2] = f16x2(e0a.z, e1a.z);
            d[3] = f16x2(e0a.w, e1a.w);
            d[4] = f16x2(e0b.x, e1b.x);
            d[5] = f16x2(e0b.y, e1b.y);
            d[6] = f16x2(e0b.z, e1b.z);
            d[7] = f16x2(e0b.w, e1b.w);
        }
    }

    // Q A-fragment (rows wid*16 + {g, g+8}, k-dims {t, t+4}).
    const float* qb = g_Q + (bh * Ll + qt * 128 + wid * 16) * PAD;
    const uint32_t qa0 = __float_as_uint(qb[g * 8 + t]);
    const uint32_t qa1 = __float_as_uint(qb[(g + 8) * 8 + t]);
    const uint32_t qa2 = __float_as_uint(qb[g * 8 + t + 4]);
    const uint32_t qa3 = __float_as_uint(qb[(g + 8) * 8 + t + 4]);
    __syncthreads();

    float o0 = 0.f, o1 = 0.f, o2 = 0.f, o3 = 0.f;   // out frag (cols=dims, col7=denom)

    const uint32_t* Vpu = (const uint32_t*)Vp;
    const float* KTt0 = KT + t * 1032;
    const float* KTt4 = KT + (t + 4) * 1032;

#pragma unroll 4
    for (int c = 0; c < 64; ++c) {
        const int k0 = c * 16;
        // --- QK: two 8-key tf32 MMAs (scores in log2 domain) ---
        uint32_t ka0 = __float_as_uint(KTt0[k0 + g]);
        uint32_t ka1 = __float_as_uint(KTt4[k0 + g]);
        uint32_t kb0 = __float_as_uint(KTt0[k0 + 8 + g]);
        uint32_t kb1 = __float_as_uint(KTt4[k0 + 8 + g]);
        float sa0 = 0.f, sa1 = 0.f, sa2 = 0.f, sa3 = 0.f;
        float sb0 = 0.f, sb1 = 0.f, sb2 = 0.f, sb3 = 0.f;
        mma_tf32_k8(sa0, sa1, sa2, sa3, qa0, qa1, qa2, qa3, ka0, ka1);
        mma_tf32_k8(sb0, sb1, sb2, sb3, qa0, qa1, qa2, qa3, kb0, kb1);

        // --- pack scores to f16x2, one packed MUFU exp per pair ---
        uint32_t wa0 = ex2h2(f16x2(sa0, sa1));
        uint32_t wa1 = ex2h2(f16x2(sa2, sa3));
        uint32_t wa2 = ex2h2(f16x2(sb0, sb1));
        uint32_t wa3 = ex2h2(f16x2(sb2, sb3));

        // --- AV: one k16 fp16 MMA; B-frag from packed V (conflict-free) ---
        uint32_t vb0 = Vpu[(c * 8 + t) * 8 + g];
        uint32_t vb1 = Vpu[(c * 8 + t + 4) * 8 + g];
        mma_f16_k16(o0, o1, o2, o3, wa0, wa1, wa2, wa3, vb0, vb1);
    }

    // Denominator = col 7, held by lane (g,3) in o1 (row g) / o3 (row g+8).
    float sum0 = __shfl_sync(0xffffffffu, o1, (lid & ~3) | 3);
    float sum1 = __shfl_sync(0xffffffffu, o3, (lid & ~3) | 3);
    float i0 = 1.0f / sum0, i1 = 1.0f / sum1;

    const int row = bh * Ll + qt * 128 + wid * 16 + g;
    float* p0 = out + row * Dd;
    float* p1 = out + (row + 8) * Dd;
    p0[2 * t] = o0 * i0;
    p1[2 * t] = o2 * i1;
    if (t < 3) {
        p0[2 * t + 1] = o1 * i0;
        p1[2 * t + 1] = o3 * i1;
    }
}

extern "C" void kernel_launch(void* const* d_in, const int* in_sizes, int n_in,
                              void* d_out, int out_size)
{
    const float* x  = (const float*)d_in[0];
    const float* Wq = (const float*)d_in[1];
    const float* bq = (const float*)d_in[2];
    const float* Wk = (const float*)d_in[3];
    const float* bk = (const float*)d_in[4];
    const float* Wv = (const float*)d_in[5];
    const float* bv = (const float*)d_in[6];

    // SMEM: proj 112*116*4 + 64*116*4 + 448 = 82112 B; attn 49408 B.
    cudaFuncSetAttribute(proj_kernel, cudaFuncAttributeMaxDynamicSharedMemorySize, 82112);
    cudaFuncSetAttribute(attn_kernel, cudaFuncAttributeMaxDynamicSharedMemorySize, 49408);

    proj_kernel<<<dim3(64, 3, 1), 256, 82112>>>(x, Wq, bq, Wk, bk, Wv, bv);
    attn_kernel<<<dim3(8, 128, 1), 256, 49408>>>((float*)d_out);
}

// round 15
// speedup vs baseline: 1.3314x; 1.0825x over previous
#include <cuda_runtime.h>
#include <cuda_fp16.h>
#include <cstdint>

#define Nn 8
#define Cc 16
#define Ll 1024
#define Dd 7
#define Hh 16
#define SZ 112
#define PAD 8

// Scratch: Q/K in [bh, l, 8] (tf32-domain; Q pre-scaled by log2(e)/32);
// V in [bh, l, 8] fp32 with pad dim = 1.0 (becomes softmax denom via MMA).
__device__ float g_Q[Nn * Hh * Ll * PAD];
__device__ float g_K[Nn * Hh * Ll * PAD];
__device__ float g_V[Nn * Hh * Ll * PAD];

__device__ __forceinline__ float tf32r(float x) {
    uint32_t u; asm("cvt.rna.tf32.f32 %0, %1;" : "=r"(u) : "f"(x));
    return __uint_as_float(u);
}
// Pack two fp32 into one f16x2 register (lo = a, hi = b).
__device__ __forceinline__ uint32_t f16x2(float a, float b) {
    uint32_t r;
    asm("cvt.rn.f16x2.f32 %0, %1, %2;" : "=r"(r) : "f"(b), "f"(a));
    return r;
}
// Packed fp16 2^x (one MUFU op for two values).
__device__ __forceinline__ uint32_t ex2h2(uint32_t x) {
    uint32_t y; asm("ex2.approx.f16x2 %0, %1;" : "=r"(y) : "r"(x)); return y;
}
// D += A(16x8) @ B(8x8), tf32 in, fp32 accum.
__device__ __forceinline__ void mma_tf32_k8(float& d0, float& d1, float& d2, float& d3,
                                            uint32_t a0, uint32_t a1, uint32_t a2, uint32_t a3,
                                            uint32_t b0, uint32_t b1) {
    asm volatile(
        "mma.sync.aligned.m16n8k8.row.col.f32.tf32.tf32.f32 "
        "{%0,%1,%2,%3}, {%4,%5,%6,%7}, {%8,%9}, {%0,%1,%2,%3};"
        : "+f"(d0), "+f"(d1), "+f"(d2), "+f"(d3)
        : "r"(a0), "r"(a1), "r"(a2), "r"(a3), "r"(b0), "r"(b1));
}
// D += A(16x16) @ B(16x8), fp16 in, fp32 accum.
__device__ __forceinline__ void mma_f16_k16(float& d0, float& d1, float& d2, float& d3,
                                            uint32_t a0, uint32_t a1, uint32_t a2, uint32_t a3,
                                            uint32_t b0, uint32_t b1) {
    asm volatile(
        "mma.sync.aligned.m16n8k16.row.col.f32.f16.f16.f32 "
        "{%0,%1,%2,%3}, {%4,%5,%6,%7}, {%8,%9}, {%0,%1,%2,%3};"
        : "+f"(d0), "+f"(d1), "+f"(d2), "+f"(d3)
        : "r"(a0), "r"(a1), "r"(a2), "r"(a3), "r"(b0), "r"(b1));
}

// ---------------------------------------------------------------------------
// Tensor-core projection v3b: q/k/v = xf @ W^T + b -> [bh, l, 8].
// Grid (64 blocks of 128 rows, 3 matrices), 256 threads (8 warps).
// W staged once per CTA (o-major). Epilogue goes through SMEM
// (Os[64][133], reusing the As region; output column o = head*7+dim) and
// writes GMEM as coalesced STG.128 pairs. Stride 133 -> conflict-free
// LDS in the store pass (bank 5r mod 32). Pad dim composed in-register.
// ---------------------------------------------------------------------------
__global__ __launch_bounds__(256) void proj_kernel(
    const float* __restrict__ x,
    const float* __restrict__ Wq, const float* __restrict__ bq,
    const float* __restrict__ Wk, const float* __restrict__ bk,
    const float* __restrict__ Wv, const float* __restrict__ bv)
{
    extern __shared__ float sm[];
    float* Wt = sm;                     // [112][116] o-major: Wt[o*116+i]
    float* As = sm + 112 * 116;         // [64][116] (overlaid with Os below)
    float* Os = As;                     // [64][133] output tile (reuses As)
    float* bs = As + 64 * 133;          // [112]

    const int z = blockIdx.y;
    const float* W = (z == 0) ? Wq : ((z == 1) ? Wk : Wv);
    const float* b = (z == 0) ? bq : ((z == 1) ? bk : bv);
    float* dst     = (z == 0) ? g_Q : ((z == 1) ? g_K : g_V);
    const float scale = (z == 0) ? (1.4426950408889634f / 32.0f) : 1.0f;
    const float padv  = (z == 2) ? 1.0f : 0.0f;
    const bool  do_tf = (z != 2);

    const int tid = threadIdx.x;
    const int nb  = (blockIdx.x * 128) >> 10;   // batch (constant per CTA)

    // Stage W o-major, tf32-rounded (conflict-free STS, coalesced LDG).
    for (int e = tid; e < SZ * SZ; e += 256) {
        int o = e / SZ, i = e - o * SZ;
        Wt[o * 116 + i] = tf32r(W[e]);
    }
    if (tid < SZ) bs[tid] = b[tid];

    const int wid = tid >> 5, lid = tid & 31;
    const int g = lid >> 2, t = lid & 3;
    const int rt = wid & 3;            // 16-row tile within 64 rows
    const int cw = wid >> 2;           // column half: cols cw*56

    for (int sub = 0; sub < 2; ++sub) {
        const int row0 = blockIdx.x * 128 + sub * 64;
        __syncthreads();   // W/bias ready (sub 0); As region reusable (sub 1)

        // Stage xf tile, tf32-rounded.
        for (int e = tid; e < 64 * SZ; e += 256) {
            int r = e / SZ, i = e - r * SZ;
            int l = (row0 + r) & 1023;
            int c = i / Dd, dd = i - c * Dd;
            As[r * 116 + i] = tf32r(x[(((nb * Cc + c) << 10) + l) * Dd + dd]);
        }
        __syncthreads();

        const float* A0 = As + (rt * 16 + g) * 116;
        const float* A1 = A0 + 8 * 116;

        // C-frags init with bias.
        float acc[7][4];
#pragma unroll
        for (int nt = 0; nt < 7; ++nt) {
            int n0 = cw * 56 + nt * 8;
            float b0 = bs[n0 + 2 * t], b1 = bs[n0 + 2 * t + 1];
            acc[nt][0] = b0; acc[nt][1] = b1;
            acc[nt][2] = b0; acc[nt][3] = b1;
        }

#pragma unroll
        for (int ks = 0; ks < 14; ++ks) {
            const int k0 = ks * 8;
            uint32_t a0 = __float_as_uint(A0[k0 + t]);
            uint32_t a1 = __float_as_uint(A1[k0 + t]);
            uint32_t a2 = __float_as_uint(A0[k0 + t + 4]);
            uint32_t a3 = __float_as_uint(A1[k0 + t + 4]);
            const float* B0 = Wt + (cw * 56 + g) * 116 + k0;   // o-major
#pragma unroll
            for (int nt = 0; nt < 7; ++nt) {
                uint32_t b0 = __float_as_uint(B0[nt * 8 * 116 + t]);
                uint32_t b1 = __float_as_uint(B0[nt * 8 * 116 + t + 4]);
                mma_tf32_k8(acc[nt][0], acc[nt][1], acc[nt][2], acc[nt][3],
                            a0, a1, a2, a3, b0, b1);
            }
        }
        __syncthreads();   // done reading As; Os may overwrite it

        // Stage outputs to SMEM: column o = cw*56 + nt*8 + 2t + j (0..111).
        const int rA = rt * 16 + g, rB = rA + 8;
#pragma unroll
        for (int nt = 0; nt < 7; ++nt) {
            int o0 = cw * 56 + nt * 8 + 2 * t;
#pragma unroll
            for (int j = 0; j < 2; ++j) {
                float vA = acc[nt][j]     * scale;
                float vB = acc[nt][2 + j] * scale;
                if (do_tf) { vA = tf32r(vA); vB = tf32r(vB); }
                Os[rA * 133 + o0 + j] = vA;
                Os[rB * 133 + o0 + j] = vB;
            }
        }
        __syncthreads();

        // Coalesced GMEM stores: warp spans 32 consecutive rows of one head.
        // Output column base for head h is h*7 (7 dims per head).
        for (int e = tid; e < 1024; e += 256) {
            int head = e >> 6, r = e & 63;
            const float* os = Os + r * 133 + head * 7;
            int l = (row0 + r) & 1023;
            float4* p = (float4*)(dst + (((nb * Hh + head) << 10) + l) * PAD);
            p[0] = make_float4(os[0], os[1], os[2], os[3]);
            p[1] = make_float4(os[4], os[5], os[6], padv);
        }
    }
}

// ---------------------------------------------------------------------------
// Warp-MMA attention (R11-R13, unchanged — measured 31.8us).
// ---------------------------------------------------------------------------
__global__ __launch_bounds__(256) void attn_kernel(float* __restrict__ out)
{
    extern __shared__ char smem[];
    float*   KT = (float*)smem;               // [8][1032]
    __half2* Vp = (__half2*)(smem + 33024);   // [512][8]: (V[2k],V[2k+1])[dim]

    const int tid = threadIdx.x;
    const int wid = tid >> 5, lid = tid & 31;
    const int g = lid >> 2, t = lid & 3;
    const int qt = blockIdx.x;
    const int bh = blockIdx.y;

    // Stage K^T.
    const float* gK = g_K + bh * Ll * PAD;
    for (int e = tid; e < 8192; e += 256) {
        int key = e >> 3, dim = e & 7;
        KT[dim * 1032 + key] = gK[e];
    }
    // Stage V packed: Vp[k2][dim] = half2(V[2k2][dim], V[2k2+1][dim]).
    {
        const float4* gV4 = (const float4*)(g_V + bh * Ll * PAD);
        for (int k2 = tid; k2 < 512; k2 += 256) {
            float4 e0a = gV4[k2 * 4 + 0], e0b = gV4[k2 * 4 + 1];
            float4 e1a = gV4[k2 * 4 + 2], e1b = gV4[k2 * 4 + 3];
            uint32_t* d = (uint32_t*)(Vp + k2 * 8);
            d[0] = f16x2(e0a.x, e1a.x);
            d[1] = f16x2(e0a.y, e1a.y);
            d[2] = f16x2(e0a.z, e1a.z);
            d[3] = f16x2(e0a.w, e1a.w);
            d[4] = f16x2(e0b.x, e1b.x);
            d[5] = f16x2(e0b.y, e1b.y);
            d[6] = f16x2(e0b.z, e1b.z);
            d[7] = f16x2(e0b.w, e1b.w);
        }
    }

    // Q A-fragment (rows wid*16 + {g, g+8}, k-dims {t, t+4}).
    const float* qb = g_Q + (bh * Ll + qt * 128 + wid * 16) * PAD;
    const uint32_t qa0 = __float_as_uint(qb[g * 8 + t]);
    const uint32_t qa1 = __float_as_uint(qb[(g + 8) * 8 + t]);
    const uint32_t qa2 = __float_as_uint(qb[g * 8 + t + 4]);
    const uint32_t qa3 = __float_as_uint(qb[(g + 8) * 8 + t + 4]);
    __syncthreads();

    float o0 = 0.f, o1 = 0.f, o2 = 0.f, o3 = 0.f;   // out frag (cols=dims, col7=denom)

    const uint32_t* Vpu = (const uint32_t*)Vp;
    const float* KTt0 = KT + t * 1032;
    const float* KTt4 = KT + (t + 4) * 1032;

#pragma unroll 4
    for (int c = 0; c < 64; ++c) {
        const int k0 = c * 16;
        // --- QK: two 8-key tf32 MMAs (scores in log2 domain) ---
        uint32_t ka0 = __float_as_uint(KTt0[k0 + g]);
        uint32_t ka1 = __float_as_uint(KTt4[k0 + g]);
        uint32_t kb0 = __float_as_uint(KTt0[k0 + 8 + g]);
        uint32_t kb1 = __float_as_uint(KTt4[k0 + 8 + g]);
        float sa0 = 0.f, sa1 = 0.f, sa2 = 0.f, sa3 = 0.f;
        float sb0 = 0.f, sb1 = 0.f, sb2 = 0.f, sb3 = 0.f;
        mma_tf32_k8(sa0, sa1, sa2, sa3, qa0, qa1, qa2, qa3, ka0, ka1);
        mma_tf32_k8(sb0, sb1, sb2, sb3, qa0, qa1, qa2, qa3, kb0, kb1);

        // --- pack scores to f16x2, one packed MUFU exp per pair ---
        uint32_t wa0 = ex2h2(f16x2(sa0, sa1));
        uint32_t wa1 = ex2h2(f16x2(sa2, sa3));
        uint32_t wa2 = ex2h2(f16x2(sb0, sb1));
        uint32_t wa3 = ex2h2(f16x2(sb2, sb3));

        // --- AV: one k16 fp16 MMA; B-frag from packed V (conflict-free) ---
        uint32_t vb0 = Vpu[(c * 8 + t) * 8 + g];
        uint32_t vb1 = Vpu[(c * 8 + t + 4) * 8 + g];
        mma_f16_k16(o0, o1, o2, o3, wa0, wa1, wa2, wa3, vb0, vb1);
    }

    // Denominator = col 7, held by lane (g,3) in o1 (row g) / o3 (row g+8).
    float sum0 = __shfl_sync(0xffffffffu, o1, (lid & ~3) | 3);
    float sum1 = __shfl_sync(0xffffffffu, o3, (lid & ~3) | 3);
    float i0 = 1.0f / sum0, i1 = 1.0f / sum1;

    const int row = bh * Ll + qt * 128 + wid * 16 + g;
    float* p0 = out + row * Dd;
    float* p1 = out + (row + 8) * Dd;
    p0[2 * t] = o0 * i0;
    p1[2 * t] = o2 * i1;
    if (t < 3) {
        p0[2 * t + 1] = o1 * i0;
        p1[2 * t + 1] = o3 * i1;
    }
}

extern "C" void kernel_launch(void* const* d_in, const int* in_sizes, int n_in,
                              void* d_out, int out_size)
{
    const float* x  = (const float*)d_in[0];
    const float* Wq = (const float*)d_in[1];
    const float* bq = (const float*)d_in[2];
    const float* Wk = (const float*)d_in[3];
    const float* bk = (const float*)d_in[4];
    const float* Wv = (const float*)d_in[5];
    const float* bv = (const float*)d_in[6];

    // SMEM: proj 112*116*4 + 64*133*4 + 448 = 86464 B; attn 49408 B.
    cudaFuncSetAttribute(proj_kernel, cudaFuncAttributeMaxDynamicSharedMemorySize, 86464);
    cudaFuncSetAttribute(attn_kernel, cudaFuncAttributeMaxDynamicSharedMemorySize, 49408);

    proj_kernel<<<dim3(64, 3, 1), 256, 86464>>>(x, Wq, bq, Wk, bk, Wv, bv);
    attn_kernel<<<dim3(8, 128, 1), 256, 49408>>>((float*)d_out);
}